// round 17
// baseline (speedup 1.0000x reference)
#include <cuda_runtime.h>
#include <math.h>

// Post_rois: SSD post-processing (softmax scores + box decode + greedy NMS + top-200)
// Inputs: loc [8,4096,4] f32, conf [8*4096,2] f32, prior [4096,4] f32 (cx,cy,w,h)
// Output: f32 [8, 2, 200, 5]; class-0 slice zeros, class-1 = NMS rows [s,x1,y1,x2,y2].
//
// Two kernels:
//  1) prep (wide grid): softmax -> packed sortable key for ALL priors -> global scratch
//  2) per-image (grid=8): radix-select exact top ~1024 keys, bitonic sort (EPT=8),
//     decode selected boxes, chunked NMS with smem-mask Jacobi fixpoint (1 barrier/step).

#define BATCH    8
#define NPRI     4096
#define TOPK     200
#define BLK      1024
#define CHUNK    256
#define SELCAP   1024
#define SELMIN   897
#define CONF_TH  0.01f
#define NMS_TH   0.45f

typedef unsigned long long u64;

// ---------------- global scratch (device global: allocation-free) ----------------
__device__ u64 g_keys[BATCH * NPRI];

// ---------------- dynamic smem layout (kernel 2) ----------------
#define OFF_SKEY    0                           // u64[4096]    32768
#define OFF_SSEL    (OFF_SKEY    + 32768)       // u64[1024]     8192
#define OFF_SELBOX  (OFF_SSEL    + 8192)        // float4[1024] 16384
#define OFF_SELAREA (OFF_SELBOX  + 16384)       // float[1024]   4096
#define OFF_ABOX    (OFF_SELAREA + 4096)        // float4[256]   4096
#define OFF_AAREA   (OFF_ABOX    + 4096)        // float[256]    1024
#define OFF_ASCORE  (OFF_AAREA   + 1024)        // float[256]    1024
#define OFF_KBOX    (OFF_ASCORE  + 1024)        // float4[200]   3200
#define OFF_KAREA   (OFF_KBOX    + 3200)        // float[200]     800
#define OFF_MASK    (OFF_KAREA   + 800)         // u32[8][256]   8192
#define OFF_HIST    (OFF_MASK    + 8192)        // int[8*256]    8192
#define OFF_SSUF    (OFF_HIST    + 8192)        // int[256]      1024
#define SMEM_BYTES  (OFF_SSUF    + 1024)

// ---------------- prep kernel: keys only, one prior per thread ----------------
#define P1BLK 512
__global__ __launch_bounds__(P1BLK)
void prep_kernel(const float* __restrict__ conf)
{
    int g = blockIdx.x * P1BLK + threadIdx.x;     // 0 .. BATCH*NPRI-1
    int n = g & (NPRI - 1);

    float c0 = conf[(size_t)g * 2 + 0];
    float c1 = conf[(size_t)g * 2 + 1];
    float m  = fmaxf(c0, c1);
    float e0 = expf(__fsub_rn(c0, m));
    float e1 = expf(__fsub_rn(c1, m));
    float s  = __fdiv_rn(e1, __fadd_rn(e0, e1));
    g_keys[g] = ((u64)__float_as_uint(s) << 32) | (unsigned)(NPRI - 1 - n);
}

// compare-exchange: a is the LOWER-index element. desc=true -> a gets the max.
__device__ __forceinline__ void ce(u64 &a, u64 &b, bool desc) {
    u64 lo = a < b ? a : b;
    u64 hi = a < b ? b : a;
    a = desc ? hi : lo;
    b = desc ? lo : hi;
}

__device__ __forceinline__ void local_merge8(u64 v[8], bool d) {
    ce(v[0],v[4],d); ce(v[1],v[5],d); ce(v[2],v[6],d); ce(v[3],v[7],d);
    ce(v[0],v[2],d); ce(v[1],v[3],d); ce(v[4],v[6],d); ce(v[5],v[7],d);
    ce(v[0],v[1],d); ce(v[2],v[3],d); ce(v[4],v[5],d); ce(v[6],v[7],d);
}

__device__ __forceinline__ void local_sort8(u64 v[8], bool dir8) {
    ce(v[0],v[1],true);  ce(v[2],v[3],false); ce(v[4],v[5],true);  ce(v[6],v[7],false);
    ce(v[0],v[2],true);  ce(v[1],v[3],true);  ce(v[4],v[6],false); ce(v[5],v[7],false);
    ce(v[0],v[1],true);  ce(v[2],v[3],true);  ce(v[4],v[5],false); ce(v[6],v[7],false);
    local_merge8(v, dir8);
}

__device__ __forceinline__ void shfl_stage8(u64 v[8], int d, bool dirT, int tid) {
    bool keep_max = (((tid & d) == 0) == dirT);
    #pragma unroll
    for (int r = 0; r < 8; r++) {
        u64 o = __shfl_xor_sync(0xffffffffu, v[r], d);
        v[r] = keep_max ? (v[r] > o ? v[r] : o) : (v[r] < o ? v[r] : o);
    }
}

__global__ __launch_bounds__(BLK, 1)
void post_rois_kernel(const float* __restrict__ loc,
                      const float* __restrict__ prior,
                      float* __restrict__ out)
{
    const int b    = blockIdx.x;
    const int tid  = threadIdx.x;
    const int wid  = tid >> 5;
    const int lane = tid & 31;

    extern __shared__ unsigned char smem_raw[];
    u64*      skey    = (u64*)     (smem_raw + OFF_SKEY);
    u64*      ssel    = (u64*)     (smem_raw + OFF_SSEL);
    float4*   selbox  = (float4*)  (smem_raw + OFF_SELBOX);
    float*    selarea = (float*)   (smem_raw + OFF_SELAREA);
    float4*   abox    = (float4*)  (smem_raw + OFF_ABOX);
    float*    aarea   = (float*)   (smem_raw + OFF_AAREA);
    float*    ascore  = (float*)   (smem_raw + OFF_ASCORE);
    float4*   kbox    = (float4*)  (smem_raw + OFF_KBOX);
    float*    karea   = (float*)   (smem_raw + OFF_KAREA);
    unsigned* maskm   = (unsigned*)(smem_raw + OFF_MASK);    // [8][256] word-major
    int*      hist8   = (int*)     (smem_raw + OFF_HIST);
    int*      Ssuf    = (int*)     (smem_raw + OFF_SSUF);

    __shared__ int wcnt[8], wbase[9];
    __shared__ unsigned supbuf[2][8];
    __shared__ unsigned char hsupA[3 * CHUNK];
    __shared__ int skept, sScnt, sDone, sLast, sCntAbove;
    __shared__ u64 sB, sPref;

    // ---- zero this image's output slice; stage keys in smem ----
    float* ob = out + (size_t)b * 2 * TOPK * 5;
    for (int i = tid; i < 2 * TOPK * 5; i += BLK) ob[i] = 0.0f;
    if (tid == 0) skept = 0;
    #pragma unroll
    for (int r = 0; r < 4; r++)
        skey[tid * 4 + r] = g_keys[(size_t)b * NPRI + tid * 4 + r];
    __syncthreads();

    u64 ub = 0xFFFFFFFFFFFFFFFFull;

    // =========================== round loop ===========================
    while (true) {
        // ---- radix select: B s.t. P = #{B <= key < ub} in [SELMIN, SELCAP] ----
        if (tid == 0) { sDone = 0; sLast = 0; sPref = 0; sCntAbove = 0; }
        __syncthreads();

        for (int shift = 56; shift >= 0; shift -= 8) {
            for (int h = tid; h < 8 * 256; h += BLK) hist8[h] = 0;
            __syncthreads();
            u64 pref = sPref;
            #pragma unroll
            for (int r = 0; r < 4; r++) {
                u64 key = skey[tid * 4 + r];
                if (key < ub && (shift == 56 || (key >> (shift + 8)) == pref))
                    atomicAdd(&hist8[((wid & 7) << 8) | (int)((key >> shift) & 255)], 1);
            }
            __syncthreads();
            if (tid < 256) {
                int s0 = 0;
                #pragma unroll
                for (int q = 0; q < 8; q++) s0 += hist8[(q << 8) | tid];
                Ssuf[tid] = s0;
            }
            __syncthreads();
            if (tid < 32) {
                int v0[8];
                #pragma unroll
                for (int q = 0; q < 8; q++) v0[q] = Ssuf[(lane << 3) + q];
                #pragma unroll
                for (int q = 6; q >= 0; q--) v0[q] += v0[q + 1];
                int mytot = v0[0];
                int inc = mytot;
                #pragma unroll
                for (int d = 1; d < 32; d <<= 1) {
                    int o = __shfl_down_sync(0xffffffffu, inc, d);
                    if (lane + d < 32) inc += o;
                }
                int excl = inc - mytot;
                int ca = sCntAbove;
                int best = 1 << 20;
                #pragma unroll
                for (int q = 0; q < 8; q++) {
                    int bb = (lane << 3) + q;
                    if (ca + v0[q] + excl <= SELCAP) best = min(best, bb);
                }
                #pragma unroll
                for (int d = 16; d >= 1; d >>= 1)
                    best = min(best, __shfl_xor_sync(0xffffffffu, best, d));
                int sval = 0;
                if (best < 256) {
                    int idx = best & 7;
                    int myS = v0[0];
                    #pragma unroll
                    for (int q = 1; q < 8; q++) myS = (idx == q) ? v0[q] : myS;
                    myS += excl;
                    sval = __shfl_sync(0xffffffffu, myS, best >> 3);
                }
                if (lane == 0) {
                    int Pacc = ca + sval;
                    bool accept = (best < 256) &&
                                  ((Pacc >= SELMIN) || (shift == 56 && best == 0));
                    if (accept) {
                        sDone = 1;
                        sB = ((sPref << 8) | (u64)best) << shift;
                        sLast = (shift == 56 && best == 0) ? 1 : 0;
                    } else {
                        int bdesc = (best < 256) ? best - 1 : 255;
                        sPref = (sPref << 8) | (u64)bdesc;
                        sCntAbove = ca + sval;
                    }
                }
            }
            __syncthreads();
            if (sDone) break;
        }

        // ---- compact selected keys (unordered; sort follows) ----
        if (tid == 0) sScnt = 0;
        ssel[tid] = 0;
        __syncthreads();
        u64 B = sB;
        #pragma unroll
        for (int r = 0; r < 4; r++) {
            u64 key = skey[tid * 4 + r];
            if (key >= B && key < ub) {
                int pos = atomicAdd(&sScnt, 1);
                ssel[pos] = key;
            }
        }
        __syncthreads();

        // ---- bitonic sort 1024 (descending), EPT=8 on threads 0..127 ----
        u64 v[8];
        if (tid < 128) {
            #pragma unroll
            for (int r = 0; r < 8; r++) v[r] = ssel[tid * 8 + r];
            local_sort8(v, (tid & 1) == 0);
            for (int k = 16; k <= 256; k <<= 1) {           // fully warp-local
                bool dirT = ((tid & (k >> 3)) == 0);
                for (int d = (k >> 4); d >= 1; d >>= 1) shfl_stage8(v, d, dirT, tid);
                local_merge8(v, dirT);
            }
        }
        for (int k = 512; k <= SELCAP; k <<= 1) {
            if (tid < 128) {
                #pragma unroll
                for (int r = 0; r < 8; r++) ssel[tid * 8 + r] = v[r];
            }
            __syncthreads();
            for (int j = (k >> 1); j >= 256; j >>= 1) {
                if (tid < 512) {
                    int i = ((tid & ~(j - 1)) << 1) | (tid & (j - 1));
                    int p = i | j;
                    u64 a = ssel[i], c = ssel[p];
                    bool desc = ((i & k) == 0);
                    if (desc ? (a < c) : (a > c)) { ssel[i] = c; ssel[p] = a; }
                }
                __syncthreads();
            }
            if (tid < 128) {
                #pragma unroll
                for (int r = 0; r < 8; r++) v[r] = ssel[tid * 8 + r];
                bool dirT = ((tid & (k >> 3)) == 0);
                for (int d = 16; d >= 1; d >>= 1) shfl_stage8(v, d, dirT, tid);
                local_merge8(v, dirT);
            }
        }
        if (tid < 128) {
            #pragma unroll
            for (int r = 0; r < 8; r++) ssel[tid * 8 + r] = v[r];
        }
        __syncthreads();

        // ---- decode selected boxes (pinned IEEE, no FMA), one per thread ----
        {
            int n = NPRI - 1 - (int)(unsigned)(ssel[tid] & 0xffffffffu);
            const float* lp = loc + ((size_t)b * NPRI + n) * 4;
            float lx = lp[0], ly = lp[1], lw = lp[2], lh = lp[3];
            float pcx = prior[n * 4 + 0], pcy = prior[n * 4 + 1];
            float pw  = prior[n * 4 + 2], ph  = prior[n * 4 + 3];

            float cx = __fadd_rn(pcx, __fmul_rn(__fmul_rn(lx, 0.1f), pw));
            float cy = __fadd_rn(pcy, __fmul_rn(__fmul_rn(ly, 0.1f), ph));
            float w  = __fmul_rn(pw, expf(__fmul_rn(lw, 0.2f)));
            float h  = __fmul_rn(ph, expf(__fmul_rn(lh, 0.2f)));
            float hw = __fmul_rn(w, 0.5f);
            float hh = __fmul_rn(h, 0.5f);
            float x1 = __fsub_rn(cx, hw), y1 = __fsub_rn(cy, hh);
            float x2 = __fadd_rn(cx, hw), y2 = __fadd_rn(cy, hh);

            selbox[tid]  = make_float4(x1, y1, x2, y2);
            selarea[tid] = __fmul_rn(__fsub_rn(x2, x1), __fsub_rn(y2, y1));
        }
        __syncthreads();

        // ---- chunked NMS, 4 threads/candidate, smem-mask Jacobi fixpoint ----
        const int grp = tid >> 8;                 // 0..3
        const int ci  = tid & (CHUNK - 1);
        const bool primary = (grp == 0);
        const int wlo = grp << 1;                 // this group's 2 mask words

        for (int c0 = 0; c0 < SELCAP; c0 += CHUNK) {
            if (skept >= TOPK) break;
            float topS = __uint_as_float((unsigned)(ssel[c0] >> 32));
            if (!(topS > CONF_TH)) break;

            // step 1: candidate vs already-kept boxes (k split 4 ways)
            int   gi = c0 + ci;
            float s  = __uint_as_float((unsigned)(ssel[gi] >> 32));
            bool  okp = (s > CONF_TH);
            float4 bi = selbox[gi];
            float  ai = selarea[gi];

            int K = skept;
            for (int k = grp; k < K; k += 4) {
                if (okp) {
                    float4 bj = kbox[k];
                    float iw = fmaxf(__fsub_rn(fminf(bi.z, bj.z), fmaxf(bi.x, bj.x)), 0.0f);
                    float ih = fmaxf(__fsub_rn(fminf(bi.w, bj.w), fmaxf(bi.y, bj.y)), 0.0f);
                    float inter = __fmul_rn(iw, ih);
                    if (inter > 0.0f) {
                        float denom = __fsub_rn(__fadd_rn(karea[k], ai), inter);
                        if (__fdiv_rn(inter, denom) > NMS_TH) okp = false;
                    }
                }
            }
            if (!primary) hsupA[((grp - 1) << 8) + ci] = okp ? 0 : 1;
            __syncthreads();
            bool ok = primary && okp && !hsupA[ci] && !hsupA[CHUNK + ci] && !hsupA[2 * CHUNK + ci];

            // order-preserving compaction of survivors (primaries: warps 0..7)
            unsigned bal = __ballot_sync(0xffffffffu, ok);
            if (lane == 0 && wid < 8) wcnt[wid] = __popc(bal);
            __syncthreads();
            if (tid < 32) {
                int c = (lane < 8) ? wcnt[lane] : 0;
                #pragma unroll
                for (int d = 1; d < 8; d <<= 1) {
                    int o = __shfl_up_sync(0xffffffffu, c, d);
                    if (lane >= d) c += o;
                }
                if (lane < 8) wbase[lane + 1] = c;
                if (lane == 0) wbase[0] = 0;
            }
            if (tid < 16) supbuf[tid >> 3][tid & 7] = 0;
            __syncthreads();
            int A = wbase[8];
            if (ok) {
                int pos = wbase[wid] + __popc(bal & ((1u << lane) - 1));
                abox[pos]   = bi;
                aarea[pos]  = ai;
                ascore[pos] = s;
            }
            __syncthreads();
            if (A == 0) continue;

            // step 2: suppressor mask words [wlo, wlo+1] -> smem (word-major)
            float4 bc = abox[ci < A ? ci : 0];
            float  ac = aarea[ci < A ? ci : 0];
            #pragma unroll
            for (int w = 0; w < 2; w++) {
                unsigned bits = 0;
                int rbase = (wlo + w) << 5;
                if (ci < A && rbase < ci) {
                    int rend = ci - rbase; if (rend > 32) rend = 32;
                    for (int rr = 0; rr < rend; rr++) {
                        float4 br = abox[rbase + rr];
                        float iw = fmaxf(__fsub_rn(fminf(bc.z, br.z), fmaxf(bc.x, br.x)), 0.0f);
                        float ih = fmaxf(__fsub_rn(fminf(bc.w, br.w), fmaxf(bc.y, br.y)), 0.0f);
                        float inter = __fmul_rn(iw, ih);
                        if (inter > 0.0f) {
                            float denom = __fsub_rn(__fadd_rn(aarea[rbase + rr], ac), inter);
                            if (__fdiv_rn(inter, denom) > NMS_TH) bits |= (1u << rr);
                        }
                    }
                }
                maskm[((wlo + w) << 8) + ci] = bits;
            }
            __syncthreads();

            // step 3: Jacobi fixpoint, 1 barrier per step (double-buffered supvec)
            bool sup = false;
            int cur = 0;
            for (int it = 0; it <= A; it++) {
                bool changed = false;
                if (primary) {
                    unsigned acc = 0;
                    #pragma unroll
                    for (int w = 0; w < 8; w++)
                        acc |= (maskm[(w << 8) + ci] & ~supbuf[cur][w]);
                    bool ns = (acc != 0);
                    changed = (ns != sup);
                    sup = ns;
                }
                unsigned sb = __ballot_sync(0xffffffffu, sup);
                if (lane == 0 && wid < 8) supbuf[cur ^ 1][wid] = sb;
                cur ^= 1;
                if (!__syncthreads_or(changed)) break;
            }

            // ordered compaction of kept, parallel output + kept-set append
            bool kept = primary && (ci < A) && !sup;
            unsigned kb = __ballot_sync(0xffffffffu, kept);
            if (lane == 0 && wid < 8) wcnt[wid] = __popc(kb);
            __syncthreads();
            if (tid < 32) {
                int c = (lane < 8) ? wcnt[lane] : 0;
                #pragma unroll
                for (int d = 1; d < 8; d <<= 1) {
                    int o = __shfl_up_sync(0xffffffffu, c, d);
                    if (lane >= d) c += o;
                }
                if (lane < 8) wbase[lane + 1] = c;
                if (lane == 0) wbase[0] = 0;
            }
            __syncthreads();
            int total = wbase[8];
            if (kept) {
                int pos = skept + wbase[wid] + __popc(kb & ((1u << lane) - 1));
                if (pos < TOPK) {
                    kbox[pos]  = bc;
                    karea[pos] = ac;
                    float* row = ob + (size_t)(TOPK + pos) * 5;
                    row[0] = ascore[ci];
                    row[1] = bc.x; row[2] = bc.y; row[3] = bc.z; row[4] = bc.w;
                }
            }
            __syncthreads();
            if (tid == 0) {
                int nk = skept + total;
                skept = nk < TOPK ? nk : TOPK;
            }
            __syncthreads();
        }

        // ---- round continuation (uniform): more valid keys below B? ----
        __syncthreads();
        float bscore = __uint_as_float((unsigned)(sB >> 32));
        bool more = (skept < TOPK) && (!sLast) && (bscore > CONF_TH);
        if (!more) break;
        ub = sB;
        __syncthreads();
    }
}

extern "C" void kernel_launch(void* const* d_in, const int* in_sizes, int n_in,
                              void* d_out, int out_size)
{
    const float* loc   = (const float*)d_in[0];
    const float* conf  = (const float*)d_in[1];
    const float* prior = (const float*)d_in[2];
    float* out = (float*)d_out;

    prep_kernel<<<(BATCH * NPRI) / P1BLK, P1BLK>>>(conf);

    cudaFuncSetAttribute(post_rois_kernel,
                         cudaFuncAttributeMaxDynamicSharedMemorySize, SMEM_BYTES);
    post_rois_kernel<<<BATCH, BLK, SMEM_BYTES>>>(loc, prior, out);
}